// round 1
// baseline (speedup 1.0000x reference)
#include <cuda_runtime.h>
#include <math.h>
#include <stdint.h>

#define SEQ 2048
#define HID 2048
#define NH 32
#define NKV 8
#define HD 64
#define KVW (NKV*HD)   /* 512 */

// ---------------- scratch (static device arrays; no allocation) ----------------
__device__ float g_q[SEQ * HID];      // 16 MB
__device__ float g_k[SEQ * KVW];      // 4 MB
__device__ float g_v[SEQ * KVW];      // 4 MB
__device__ float g_att[SEQ * HID];    // 16 MB

// ---------------- generic tiled SGEMM: C[M,N] = A[M,K] @ B[K,N], row-major ----
// BM=BN=128, BK=8, 256 threads, 8x8 micro-tile per thread.
__global__ __launch_bounds__(256)
void sgemm128(const float* __restrict__ A, const float* __restrict__ B,
              float* __restrict__ C, int M, int N, int K)
{
    __shared__ float As[8][128];
    __shared__ float Bs[8][128];

    const int tid = threadIdx.x;
    const int bx = blockIdx.x;   // over N
    const int by = blockIdx.y;   // over M

    const int arow = tid >> 1;          // 0..127
    const int acol = (tid & 1) * 4;     // 0 or 4
    const int brow = tid >> 5;          // 0..7
    const int bcol = (tid & 31) * 4;    // 0..124

    const float* Ab = A + (size_t)(by * 128) * K;
    const float* Bb = B + bx * 128;

    const int tr = (tid >> 4) * 8;      // 0..120
    const int tc = (tid & 15) * 8;      // 0..120

    float acc[8][8];
#pragma unroll
    for (int i = 0; i < 8; i++)
#pragma unroll
        for (int j = 0; j < 8; j++) acc[i][j] = 0.f;

    for (int k0 = 0; k0 < K; k0 += 8) {
        float4 a4 = *(const float4*)(Ab + (size_t)arow * K + k0 + acol);
        As[acol + 0][arow] = a4.x;
        As[acol + 1][arow] = a4.y;
        As[acol + 2][arow] = a4.z;
        As[acol + 3][arow] = a4.w;
        float4 b4 = *(const float4*)(Bb + (size_t)(k0 + brow) * N + bcol);
        *(float4*)&Bs[brow][bcol] = b4;
        __syncthreads();

#pragma unroll
        for (int k = 0; k < 8; k++) {
            float4 ra0 = *(const float4*)&As[k][tr];
            float4 ra1 = *(const float4*)&As[k][tr + 4];
            float4 rb0 = *(const float4*)&Bs[k][tc];
            float4 rb1 = *(const float4*)&Bs[k][tc + 4];
            float ra[8] = {ra0.x, ra0.y, ra0.z, ra0.w, ra1.x, ra1.y, ra1.z, ra1.w};
            float rb[8] = {rb0.x, rb0.y, rb0.z, rb0.w, rb1.x, rb1.y, rb1.z, rb1.w};
#pragma unroll
            for (int i = 0; i < 8; i++)
#pragma unroll
                for (int j = 0; j < 8; j++) acc[i][j] += ra[i] * rb[j];
        }
        __syncthreads();
    }

    float* Cb = C + (size_t)(by * 128 + tr) * N + bx * 128 + tc;
#pragma unroll
    for (int i = 0; i < 8; i++) {
#pragma unroll
        for (int j = 0; j < 8; j += 4) {
            float4 v = make_float4(acc[i][j], acc[i][j + 1], acc[i][j + 2], acc[i][j + 3]);
            *(float4*)(Cb + (size_t)i * N + j) = v;
        }
    }
}

// ---------------- fused per-head RMSNorm + RoPE (in place) --------------------
// One warp per (s, head). Lane handles dims (lane, lane+32) which share a RoPE angle.
__global__ __launch_bounds__(256)
void norm_rope_kernel(float* __restrict__ x, const float* __restrict__ w,
                      const int* __restrict__ pos, int nheads, int rw)
{
    const int gw = (blockIdx.x * blockDim.x + threadIdx.x) >> 5;
    const int lane = threadIdx.x & 31;
    const int total = SEQ * nheads;
    if (gw >= total) return;
    const int s = gw / nheads;
    const int hh = gw - s * nheads;

    float* p = x + (size_t)s * rw + hh * HD;
    float x0 = p[lane];
    float x1 = p[lane + 32];

    float ss = x0 * x0 + x1 * x1;
#pragma unroll
    for (int o = 16; o; o >>= 1) ss += __shfl_xor_sync(0xffffffffu, ss, o);
    const float inv = rsqrtf(ss * (1.f / 64.f) + 1e-6f);
    x0 *= inv * w[lane];
    x1 *= inv * w[lane + 32];

    // inv_freq[i] = 10000^(-2i/64) = exp(-(i/32) * ln(10000))
    const float ang = (float)pos[s] * __expf(-(float)lane * (1.f / 32.f) * 9.2103403719761836f);
    float sn, c;
    sincosf(ang, &sn, &c);
    p[lane]      = x0 * c - x1 * sn;
    p[lane + 32] = x1 * c + x0 * sn;
}

// ---------------- causal flash attention --------------------------------------
// grid (qt=32, h=32), 256 threads. BM=BN=64, D=64. fp32, online softmax.
// Dynamic smem layout (floats):
//   Qs [64][68]  d-major (transposed):  Qs[d*68 + r]        (Q pre-scaled)
//   KV [64][68]  K phase: K^T  KV[d*68 + j];  V phase: KV[j*68 + d]
//   Ps [64][68]  scores/probs  Ps[r*68 + j]
//   m_s[64], l_s[64], al_s[64]
#define ATTN_SMEM_FLOATS (3 * 64 * 68 + 192)
#define ATTN_SMEM_BYTES  (ATTN_SMEM_FLOATS * 4)

__global__ __launch_bounds__(256)
void attn_kernel(const float* __restrict__ qb, const float* __restrict__ kb,
                 const float* __restrict__ vb, float* __restrict__ ob)
{
    extern __shared__ float sm[];
    float* Qs  = sm;
    float* KV  = sm + 64 * 68;
    float* Ps  = sm + 2 * 64 * 68;
    float* m_s = sm + 3 * 64 * 68;
    float* l_s = m_s + 64;
    float* al_s = l_s + 64;

    const int tid = threadIdx.x;
    const int qt  = blockIdx.x;   // q tile (64 rows)
    const int h   = blockIdx.y;   // head
    const int kvh = h >> 2;       // GQA group of 4

    if (tid < 64) { m_s[tid] = -1e30f; l_s[tid] = 0.f; }

    // load Q tile transposed, pre-scaled by 1/sqrt(64) = 0.125
    {
        const int r  = tid >> 2;
        const int d0 = (tid & 3) * 16;
        const float* src = qb + (size_t)(qt * 64 + r) * HID + h * HD + d0;
#pragma unroll
        for (int i = 0; i < 16; i += 4) {
            float4 v = *(const float4*)(src + i);
            Qs[(d0 + i + 0) * 68 + r] = v.x * 0.125f;
            Qs[(d0 + i + 1) * 68 + r] = v.y * 0.125f;
            Qs[(d0 + i + 2) * 68 + r] = v.z * 0.125f;
            Qs[(d0 + i + 3) * 68 + r] = v.w * 0.125f;
        }
    }

    const int sr0 = (tid >> 4) * 4;   // 4 q-rows per thread
    const int sc0 = (tid & 15) * 4;   // 4 cols (kv or dim) per thread
    const int lj  = tid >> 2;         // load row / softmax row
    const int ld0 = (tid & 3) * 16;   // load dim base

    float o[4][4];
#pragma unroll
    for (int i = 0; i < 4; i++)
#pragma unroll
        for (int j = 0; j < 4; j++) o[i][j] = 0.f;

    for (int kt = 0; kt <= qt; ++kt) {
        // ---- load K tile (transposed into KV) ----
        {
            const float* ksrc = kb + (size_t)(kt * 64 + lj) * KVW + kvh * HD + ld0;
#pragma unroll
            for (int i = 0; i < 16; i += 4) {
                float4 v = *(const float4*)(ksrc + i);
                KV[(ld0 + i + 0) * 68 + lj] = v.x;
                KV[(ld0 + i + 1) * 68 + lj] = v.y;
                KV[(ld0 + i + 2) * 68 + lj] = v.z;
                KV[(ld0 + i + 3) * 68 + lj] = v.w;
            }
        }
        __syncthreads();

        // ---- S = Q @ K^T (64x64), 4x4 micro-tile ----
        float s[4][4];
#pragma unroll
        for (int i = 0; i < 4; i++)
#pragma unroll
            for (int j = 0; j < 4; j++) s[i][j] = 0.f;

#pragma unroll 8
        for (int d = 0; d < 64; ++d) {
            float4 q4 = *(const float4*)(Qs + d * 68 + sr0);
            float4 k4 = *(const float4*)(KV + d * 68 + sc0);
            float qa[4] = {q4.x, q4.y, q4.z, q4.w};
            float ka[4] = {k4.x, k4.y, k4.z, k4.w};
#pragma unroll
            for (int i = 0; i < 4; i++)
#pragma unroll
                for (int j = 0; j < 4; j++) s[i][j] += qa[i] * ka[j];
        }

        if (kt == qt) {   // causal mask on diagonal tile
#pragma unroll
            for (int i = 0; i < 4; i++)
#pragma unroll
                for (int j = 0; j < 4; j++)
                    if (sc0 + j > sr0 + i) s[i][j] = -1e30f;
        }
#pragma unroll
        for (int i = 0; i < 4; i++) {
            float4 v = make_float4(s[i][0], s[i][1], s[i][2], s[i][3]);
            *(float4*)(Ps + (size_t)(sr0 + i) * 68 + sc0) = v;
        }
        __syncthreads();   // Ps ready; K no longer needed

        // ---- load V tile (natural layout) into KV ----
        {
            const float* vsrc = vb + (size_t)(kt * 64 + lj) * KVW + kvh * HD + ld0;
#pragma unroll
            for (int i = 0; i < 16; i += 4) {
                float4 v = *(const float4*)(vsrc + i);
                *(float4*)(KV + lj * 68 + ld0 + i) = v;
            }
        }

        // ---- online softmax over Ps rows (4 threads per row, 16 cols each) ----
        {
            const int row = lj;
            const int sub = tid & 3;
            float* prow = Ps + row * 68 + sub * 16;
            float vbuf[16];
            float mloc = -1e30f;
#pragma unroll
            for (int j = 0; j < 16; ++j) { vbuf[j] = prow[j]; mloc = fmaxf(mloc, vbuf[j]); }
            mloc = fmaxf(mloc, __shfl_xor_sync(0xffffffffu, mloc, 1));
            mloc = fmaxf(mloc, __shfl_xor_sync(0xffffffffu, mloc, 2));
            const float mo = m_s[row];
            const float mn = fmaxf(mo, mloc);
            float sum = 0.f;
#pragma unroll
            for (int j = 0; j < 16; ++j) {
                float pv = __expf(vbuf[j] - mn);
                prow[j] = pv;
                sum += pv;
            }
            sum += __shfl_xor_sync(0xffffffffu, sum, 1);
            sum += __shfl_xor_sync(0xffffffffu, sum, 2);
            __syncwarp();
            if (sub == 0) {
                const float a = __expf(mo - mn);
                al_s[row] = a;
                l_s[row] = l_s[row] * a + sum;
                m_s[row] = mn;
            }
        }
        __syncthreads();   // V + probs + alpha ready

        // ---- rescale O, accumulate O += P @ V ----
        float ar[4];
#pragma unroll
        for (int i = 0; i < 4; i++) ar[i] = al_s[sr0 + i];
#pragma unroll
        for (int i = 0; i < 4; i++)
#pragma unroll
            for (int j = 0; j < 4; j++) o[i][j] *= ar[i];

#pragma unroll 8
        for (int j = 0; j < 64; ++j) {
            float4 v4 = *(const float4*)(KV + j * 68 + sc0);
#pragma unroll
            for (int i = 0; i < 4; i++) {
                float p = Ps[(sr0 + i) * 68 + j];
                o[i][0] += p * v4.x;
                o[i][1] += p * v4.y;
                o[i][2] += p * v4.z;
                o[i][3] += p * v4.w;
            }
        }
        __syncthreads();   // KV free for next K tile
    }

    // ---- epilogue: divide by l, write [s, h*64 + d] ----
#pragma unroll
    for (int i = 0; i < 4; i++) {
        const float li = 1.f / l_s[sr0 + i];
        float4 v = make_float4(o[i][0] * li, o[i][1] * li, o[i][2] * li, o[i][3] * li);
        *(float4*)(ob + (size_t)(qt * 64 + sr0 + i) * HID + h * HD + sc0) = v;
    }
}

// ---------------- launch ------------------------------------------------------
extern "C" void kernel_launch(void* const* d_in, const int* in_sizes, int n_in,
                              void* d_out, int out_size)
{
    const float* hs  = (const float*)d_in[0];
    const int*   pos = (const int*)  d_in[1];
    const float* wq  = (const float*)d_in[2];
    const float* wk  = (const float*)d_in[3];
    const float* wv  = (const float*)d_in[4];
    const float* wo  = (const float*)d_in[5];
    const float* qw  = (const float*)d_in[6];
    const float* kw  = (const float*)d_in[7];
    float* out = (float*)d_out;

    float *pq, *pk, *pv, *pa;
    cudaGetSymbolAddress((void**)&pq, g_q);
    cudaGetSymbolAddress((void**)&pk, g_k);
    cudaGetSymbolAddress((void**)&pv, g_v);
    cudaGetSymbolAddress((void**)&pa, g_att);

    cudaFuncSetAttribute(attn_kernel, cudaFuncAttributeMaxDynamicSharedMemorySize,
                         ATTN_SMEM_BYTES);

    dim3 gq(HID / 128, SEQ / 128);        // 16x16
    dim3 gkv(KVW / 128, SEQ / 128);       // 4x16

    sgemm128<<<gq, 256>>>(hs, wq, pq, SEQ, HID, HID);
    sgemm128<<<gkv, 256>>>(hs, wk, pk, SEQ, KVW, HID);
    sgemm128<<<gkv, 256>>>(hs, wv, pv, SEQ, KVW, HID);

    norm_rope_kernel<<<(SEQ * NH * 32) / 256, 256>>>(pq, qw, pos, NH, HID);
    norm_rope_kernel<<<(SEQ * NKV * 32) / 256, 256>>>(pk, kw, pos, NKV, KVW);

    attn_kernel<<<dim3(SEQ / 64, NH), 256, ATTN_SMEM_BYTES>>>(pq, pk, pv, pa);

    sgemm128<<<gq, 256>>>(pa, wo, out, SEQ, HID, HID);
}

// round 3
// speedup vs baseline: 1.6966x; 1.6966x over previous
#include <cuda_runtime.h>
#include <math.h>
#include <stdint.h>

#define SEQ 2048
#define HID 2048
#define NH 32
#define NKV 8
#define HD 64
#define KVW (NKV*HD)   /* 512 */

// ---------------- scratch (static device arrays; no allocation) ----------------
__device__ float g_q[SEQ * HID];
__device__ float g_k[SEQ * KVW];
__device__ float g_v[SEQ * KVW];
__device__ float g_att[SEQ * HID];
__device__ float g_wqT[HID * HID];
__device__ float g_wkT[KVW * HID];
__device__ float g_wvT[KVW * HID];
__device__ float g_woT[HID * HID];

// ================= helpers =================
__device__ __forceinline__ uint32_t smem_u32(const void* p) {
    uint32_t a;
    asm("{ .reg .u64 t; cvta.to.shared.u64 t, %1; cvt.u32.u64 %0, t; }" : "=r"(a) : "l"(p));
    return a;
}
__device__ __forceinline__ uint32_t f2tf32(float f) {
    uint32_t r;
    asm("cvt.rna.tf32.f32 %0, %1;" : "=r"(r) : "f"(f));
    return r;
}
#define CP_ASYNC16(dst, src) \
    asm volatile("cp.async.cg.shared.global [%0], [%1], 16;" :: "r"(dst), "l"(src))
#define CP_COMMIT() asm volatile("cp.async.commit_group;" ::: "memory")
#define CP_WAIT(n)  asm volatile("cp.async.wait_group %0;" :: "n"(n) : "memory")

__device__ __forceinline__ void mma_tf32_16x8x8(float& c0, float& c1, float& c2, float& c3,
                                                uint32_t a0, uint32_t a1, uint32_t a2, uint32_t a3,
                                                uint32_t b0, uint32_t b1) {
    asm volatile(
        "mma.sync.aligned.m16n8k8.row.col.f32.tf32.tf32.f32 "
        "{%0,%1,%2,%3}, {%4,%5,%6,%7}, {%8,%9}, {%0,%1,%2,%3};"
        : "+f"(c0), "+f"(c1), "+f"(c2), "+f"(c3)
        : "r"(a0), "r"(a1), "r"(a2), "r"(a3), "r"(b0), "r"(b1));
}

// ---------------- weight transpose: out[n*K+k] = in[k*N+n] --------------------
__global__ __launch_bounds__(256)
void transpose32(const float* __restrict__ in, float* __restrict__ out, int K, int N)
{
    __shared__ float t[32][33];
    const int bx = blockIdx.x * 32;  // over N
    const int by = blockIdx.y * 32;  // over K
    const int tx = threadIdx.x, ty = threadIdx.y;
#pragma unroll
    for (int i = 0; i < 32; i += 8)
        t[ty + i][tx] = in[(size_t)(by + ty + i) * N + bx + tx];
    __syncthreads();
#pragma unroll
    for (int i = 0; i < 32; i += 8)
        out[(size_t)(bx + ty + i) * K + by + tx] = t[tx][ty + i];
}

// ---------------- tf32 mma.sync GEMM: C[M,N] = A[M,K] @ BT[N,K]^T -------------
// 128x128 tile, BK=32, 256 threads = 8 warps (4m x 2n), each warp 32x64.
// smem: A/B tiles [128][36] fp32, double-buffered, filled via cp.async.
#define GPAD 36
#define GBUF (128 * GPAD)                    /* floats per tile buffer */
#define G_SMEM_BYTES (4 * GBUF * 4)          /* A0,A1,B0,B1 = 73728 B */

__global__ __launch_bounds__(256)
void gemm_mma(const float* __restrict__ A, const float* __restrict__ BT,
              float* __restrict__ C, int M, int N, int K)
{
    extern __shared__ float sm[];
    float* sA = sm;               // [2][128][36]
    float* sB = sm + 2 * GBUF;    // [2][128][36]

    const int tid  = threadIdx.x;
    const int wid  = tid >> 5;
    const int lane = tid & 31;
    const int g    = lane >> 2;       // 0..7
    const int tg   = lane & 3;        // 0..3
    const int wm   = (wid & 3) * 32;  // warp m offset in tile
    const int wn   = (wid >> 2) * 64; // warp n offset in tile
    const int m0 = blockIdx.y * 128;
    const int n0 = blockIdx.x * 128;

    // loader mapping: 2 threads per row, 16 floats each (4x 16B cp.async)
    const int lrow  = tid >> 1;
    const int lcol  = (tid & 1) * 16;
    const float* gA = A  + (size_t)(m0 + lrow) * K + lcol;
    const float* gB = BT + (size_t)(n0 + lrow) * K + lcol;
    const uint32_t sbase = smem_u32(sm);
    const uint32_t sArow = sbase + (uint32_t)(lrow * GPAD + lcol) * 4u;
    const uint32_t sBrow = sArow + 2u * GBUF * 4u;

    float acc[2][8][4];
#pragma unroll
    for (int mt = 0; mt < 2; mt++)
#pragma unroll
        for (int nt = 0; nt < 8; nt++)
#pragma unroll
            for (int i = 0; i < 4; i++) acc[mt][nt][i] = 0.f;

    const int nch = K >> 5;

    // prefetch chunk 0 into buffer 0
    {
#pragma unroll
        for (int j = 0; j < 4; j++) {
            CP_ASYNC16(sArow + j * 16u, gA + j * 4);
            CP_ASYNC16(sBrow + j * 16u, gB + j * 4);
        }
        CP_COMMIT();
    }

    for (int c = 0; c < nch; ++c) {
        const int buf = c & 1;
        if (c + 1 < nch) {
            const uint32_t off = (uint32_t)(((c + 1) & 1) * GBUF) * 4u;
            const float* pa = gA + (c + 1) * 32;
            const float* pb = gB + (c + 1) * 32;
#pragma unroll
            for (int j = 0; j < 4; j++) {
                CP_ASYNC16(sArow + off + j * 16u, pa + j * 4);
                CP_ASYNC16(sBrow + off + j * 16u, pb + j * 4);
            }
            CP_COMMIT();
            CP_WAIT(1);
        } else {
            CP_WAIT(0);
        }
        __syncthreads();

        const float* tA = sA + buf * GBUF;
        const float* tB = sB + buf * GBUF;

#pragma unroll
        for (int ks = 0; ks < 4; ++ks) {
            const int kk = ks * 8 + tg;
            uint32_t af[2][4];
#pragma unroll
            for (int mt = 0; mt < 2; mt++) {
                const int r = wm + mt * 16 + g;
                af[mt][0] = f2tf32(tA[r * GPAD + kk]);
                af[mt][1] = f2tf32(tA[(r + 8) * GPAD + kk]);
                af[mt][2] = f2tf32(tA[r * GPAD + kk + 4]);
                af[mt][3] = f2tf32(tA[(r + 8) * GPAD + kk + 4]);
            }
            uint32_t bf[8][2];
#pragma unroll
            for (int nt = 0; nt < 8; nt++) {
                const int r = wn + nt * 8 + g;
                bf[nt][0] = f2tf32(tB[r * GPAD + kk]);
                bf[nt][1] = f2tf32(tB[r * GPAD + kk + 4]);
            }
#pragma unroll
            for (int mt = 0; mt < 2; mt++)
#pragma unroll
                for (int nt = 0; nt < 8; nt++)
                    mma_tf32_16x8x8(acc[mt][nt][0], acc[mt][nt][1],
                                    acc[mt][nt][2], acc[mt][nt][3],
                                    af[mt][0], af[mt][1], af[mt][2], af[mt][3],
                                    bf[nt][0], bf[nt][1]);
        }
        __syncthreads();
    }

    // epilogue: fragment-mapped float2 stores
#pragma unroll
    for (int mt = 0; mt < 2; mt++) {
        const int r0 = m0 + wm + mt * 16 + g;
#pragma unroll
        for (int nt = 0; nt < 8; nt++) {
            const int col = n0 + wn + nt * 8 + 2 * tg;
            *(float2*)(C + (size_t)r0 * N + col) =
                make_float2(acc[mt][nt][0], acc[mt][nt][1]);
            *(float2*)(C + (size_t)(r0 + 8) * N + col) =
                make_float2(acc[mt][nt][2], acc[mt][nt][3]);
        }
    }
}

// ---------------- fused per-head RMSNorm + RoPE (in place) --------------------
__global__ __launch_bounds__(256)
void norm_rope_kernel(float* __restrict__ x, const float* __restrict__ w,
                      const int* __restrict__ pos, int nheads, int rw)
{
    const int gw = (blockIdx.x * blockDim.x + threadIdx.x) >> 5;
    const int lane = threadIdx.x & 31;
    const int total = SEQ * nheads;
    if (gw >= total) return;
    const int s = gw / nheads;
    const int hh = gw - s * nheads;

    float* p = x + (size_t)s * rw + hh * HD;
    float x0 = p[lane];
    float x1 = p[lane + 32];

    float ss = x0 * x0 + x1 * x1;
#pragma unroll
    for (int o = 16; o; o >>= 1) ss += __shfl_xor_sync(0xffffffffu, ss, o);
    const float inv = rsqrtf(ss * (1.f / 64.f) + 1e-6f);
    x0 *= inv * w[lane];
    x1 *= inv * w[lane + 32];

    const float ang = (float)pos[s] * __expf(-(float)lane * (1.f / 32.f) * 9.2103403719761836f);
    float sn, c;
    sincosf(ang, &sn, &c);
    p[lane]      = x0 * c - x1 * sn;
    p[lane + 32] = x1 * c + x0 * sn;
}

// ---------------- causal flash attention (fp32, unchanged passing R1) ---------
#define ATTN_SMEM_FLOATS (3 * 64 * 68 + 192)
#define ATTN_SMEM_BYTES  (ATTN_SMEM_FLOATS * 4)

__global__ __launch_bounds__(256)
void attn_kernel(const float* __restrict__ qb, const float* __restrict__ kb,
                 const float* __restrict__ vb, float* __restrict__ ob)
{
    extern __shared__ float sm[];
    float* Qs  = sm;
    float* KV  = sm + 64 * 68;
    float* Ps  = sm + 2 * 64 * 68;
    float* m_s = sm + 3 * 64 * 68;
    float* l_s = m_s + 64;
    float* al_s = l_s + 64;

    const int tid = threadIdx.x;
    const int qt  = blockIdx.x;
    const int h   = blockIdx.y;
    const int kvh = h >> 2;

    if (tid < 64) { m_s[tid] = -1e30f; l_s[tid] = 0.f; }

    {
        const int r  = tid >> 2;
        const int d0 = (tid & 3) * 16;
        const float* src = qb + (size_t)(qt * 64 + r) * HID + h * HD + d0;
#pragma unroll
        for (int i = 0; i < 16; i += 4) {
            float4 v = *(const float4*)(src + i);
            Qs[(d0 + i + 0) * 68 + r] = v.x * 0.125f;
            Qs[(d0 + i + 1) * 68 + r] = v.y * 0.125f;
            Qs[(d0 + i + 2) * 68 + r] = v.z * 0.125f;
            Qs[(d0 + i + 3) * 68 + r] = v.w * 0.125f;
        }
    }

    const int sr0 = (tid >> 4) * 4;
    const int sc0 = (tid & 15) * 4;
    const int lj  = tid >> 2;
    const int ld0 = (tid & 3) * 16;

    float o[4][4];
#pragma unroll
    for (int i = 0; i < 4; i++)
#pragma unroll
        for (int j = 0; j < 4; j++) o[i][j] = 0.f;

    for (int kt = 0; kt <= qt; ++kt) {
        {
            const float* ksrc = kb + (size_t)(kt * 64 + lj) * KVW + kvh * HD + ld0;
#pragma unroll
            for (int i = 0; i < 16; i += 4) {
                float4 v = *(const float4*)(ksrc + i);
                KV[(ld0 + i + 0) * 68 + lj] = v.x;
                KV[(ld0 + i + 1) * 68 + lj] = v.y;
                KV[(ld0 + i + 2) * 68 + lj] = v.z;
                KV[(ld0 + i + 3) * 68 + lj] = v.w;
            }
        }
        __syncthreads();

        float s[4][4];
#pragma unroll
        for (int i = 0; i < 4; i++)
#pragma unroll
            for (int j = 0; j < 4; j++) s[i][j] = 0.f;

#pragma unroll 8
        for (int d = 0; d < 64; ++d) {
            float4 q4 = *(const float4*)(Qs + d * 68 + sr0);
            float4 k4 = *(const float4*)(KV + d * 68 + sc0);
            float qa[4] = {q4.x, q4.y, q4.z, q4.w};
            float ka[4] = {k4.x, k4.y, k4.z, k4.w};
#pragma unroll
            for (int i = 0; i < 4; i++)
#pragma unroll
                for (int j = 0; j < 4; j++) s[i][j] += qa[i] * ka[j];
        }

        if (kt == qt) {
#pragma unroll
            for (int i = 0; i < 4; i++)
#pragma unroll
                for (int j = 0; j < 4; j++)
                    if (sc0 + j > sr0 + i) s[i][j] = -1e30f;
        }
#pragma unroll
        for (int i = 0; i < 4; i++) {
            float4 v = make_float4(s[i][0], s[i][1], s[i][2], s[i][3]);
            *(float4*)(Ps + (size_t)(sr0 + i) * 68 + sc0) = v;
        }
        __syncthreads();

        {
            const float* vsrc = vb + (size_t)(kt * 64 + lj) * KVW + kvh * HD + ld0;
#pragma unroll
            for (int i = 0; i < 16; i += 4) {
                float4 v = *(const float4*)(vsrc + i);
                *(float4*)(KV + lj * 68 + ld0 + i) = v;
            }
        }

        {
            const int row = lj;
            const int sub = tid & 3;
            float* prow = Ps + row * 68 + sub * 16;
            float vbuf[16];
            float mloc = -1e30f;
#pragma unroll
            for (int j = 0; j < 16; ++j) { vbuf[j] = prow[j]; mloc = fmaxf(mloc, vbuf[j]); }
            mloc = fmaxf(mloc, __shfl_xor_sync(0xffffffffu, mloc, 1));
            mloc = fmaxf(mloc, __shfl_xor_sync(0xffffffffu, mloc, 2));
            const float mo = m_s[row];
            const float mn = fmaxf(mo, mloc);
            float sum = 0.f;
#pragma unroll
            for (int j = 0; j < 16; ++j) {
                float pv = __expf(vbuf[j] - mn);
                prow[j] = pv;
                sum += pv;
            }
            sum += __shfl_xor_sync(0xffffffffu, sum, 1);
            sum += __shfl_xor_sync(0xffffffffu, sum, 2);
            __syncwarp();
            if (sub == 0) {
                const float a = __expf(mo - mn);
                al_s[row] = a;
                l_s[row] = l_s[row] * a + sum;
                m_s[row] = mn;
            }
        }
        __syncthreads();

        float ar[4];
#pragma unroll
        for (int i = 0; i < 4; i++) ar[i] = al_s[sr0 + i];
#pragma unroll
        for (int i = 0; i < 4; i++)
#pragma unroll
            for (int j = 0; j < 4; j++) o[i][j] *= ar[i];

#pragma unroll 8
        for (int j = 0; j < 64; ++j) {
            float4 v4 = *(const float4*)(KV + j * 68 + sc0);
#pragma unroll
            for (int i = 0; i < 4; i++) {
                float p = Ps[(sr0 + i) * 68 + j];
                o[i][0] += p * v4.x;
                o[i][1] += p * v4.y;
                o[i][2] += p * v4.z;
                o[i][3] += p * v4.w;
            }
        }
        __syncthreads();
    }

#pragma unroll
    for (int i = 0; i < 4; i++) {
        const float li = 1.f / l_s[sr0 + i];
        float4 v = make_float4(o[i][0] * li, o[i][1] * li, o[i][2] * li, o[i][3] * li);
        *(float4*)(ob + (size_t)(qt * 64 + sr0 + i) * HID + h * HD + sc0) = v;
    }
}

// ---------------- launch ------------------------------------------------------
extern "C" void kernel_launch(void* const* d_in, const int* in_sizes, int n_in,
                              void* d_out, int out_size)
{
    const float* hs  = (const float*)d_in[0];
    const int*   pos = (const int*)  d_in[1];
    const float* wq  = (const float*)d_in[2];
    const float* wk  = (const float*)d_in[3];
    const float* wv  = (const float*)d_in[4];
    const float* wo  = (const float*)d_in[5];
    const float* qw  = (const float*)d_in[6];
    const float* kw  = (const float*)d_in[7];
    float* out = (float*)d_out;

    float *pq, *pk, *pv, *pa, *pwqT, *pwkT, *pwvT, *pwoT;
    cudaGetSymbolAddress((void**)&pq, g_q);
    cudaGetSymbolAddress((void**)&pk, g_k);
    cudaGetSymbolAddress((void**)&pv, g_v);
    cudaGetSymbolAddress((void**)&pa, g_att);
    cudaGetSymbolAddress((void**)&pwqT, g_wqT);
    cudaGetSymbolAddress((void**)&pwkT, g_wkT);
    cudaGetSymbolAddress((void**)&pwvT, g_wvT);
    cudaGetSymbolAddress((void**)&pwoT, g_woT);

    cudaFuncSetAttribute(attn_kernel, cudaFuncAttributeMaxDynamicSharedMemorySize,
                         ATTN_SMEM_BYTES);
    cudaFuncSetAttribute(gemm_mma, cudaFuncAttributeMaxDynamicSharedMemorySize,
                         G_SMEM_BYTES);

    // transpose weights to [N, K]
    dim3 tb(32, 8);
    transpose32<<<dim3(HID / 32, HID / 32), tb>>>(wq, pwqT, HID, HID);
    transpose32<<<dim3(KVW / 32, HID / 32), tb>>>(wk, pwkT, HID, KVW);
    transpose32<<<dim3(KVW / 32, HID / 32), tb>>>(wv, pwvT, HID, KVW);
    transpose32<<<dim3(HID / 32, HID / 32), tb>>>(wo, pwoT, HID, HID);

    // projections (tf32 mma.sync)
    gemm_mma<<<dim3(HID / 128, SEQ / 128), 256, G_SMEM_BYTES>>>(hs, pwqT, pq, SEQ, HID, HID);
    gemm_mma<<<dim3(KVW / 128, SEQ / 128), 256, G_SMEM_BYTES>>>(hs, pwkT, pk, SEQ, KVW, HID);
    gemm_mma<<<dim3(KVW / 128, SEQ / 128), 256, G_SMEM_BYTES>>>(hs, pwvT, pv, SEQ, KVW, HID);

    norm_rope_kernel<<<(SEQ * NH * 32) / 256, 256>>>(pq, qw, pos, NH, HID);
    norm_rope_kernel<<<(SEQ * NKV * 32) / 256, 256>>>(pk, kw, pos, NKV, KVW);

    attn_kernel<<<dim3(SEQ / 64, NH), 256, ATTN_SMEM_BYTES>>>(pq, pk, pv, pa);

    gemm_mma<<<dim3(HID / 128, SEQ / 128), 256, G_SMEM_BYTES>>>(pa, pwoT, out, SEQ, HID, HID);
}

// round 5
// speedup vs baseline: 2.5239x; 1.4876x over previous
#include <cuda_runtime.h>
#include <math.h>
#include <stdint.h>

#define SEQ 2048
#define HID 2048
#define NH 32
#define NKV 8
#define HD 64
#define KVW (NKV*HD)   /* 512 */

// ---------------- scratch (static device arrays; no allocation) ----------------
__device__ float g_q[SEQ * HID];
__device__ float g_k[SEQ * KVW];
__device__ float g_v[SEQ * KVW];
__device__ float g_att[SEQ * HID];
__device__ float g_wqT[HID * HID];
__device__ float g_wkT[KVW * HID];
__device__ float g_wvT[KVW * HID];
__device__ float g_woT[HID * HID];

// ================= helpers =================
__device__ __forceinline__ uint32_t smem_u32(const void* p) {
    uint32_t a;
    asm("{ .reg .u64 t; cvta.to.shared.u64 t, %1; cvt.u32.u64 %0, t; }" : "=r"(a) : "l"(p));
    return a;
}
__device__ __forceinline__ uint32_t f2tf32(float f) {
    uint32_t r;
    asm("cvt.rna.tf32.f32 %0, %1;" : "=r"(r) : "f"(f));
    return r;
}
#define CP_ASYNC16(dst, src) \
    asm volatile("cp.async.cg.shared.global [%0], [%1], 16;" :: "r"(dst), "l"(src))
#define CP_COMMIT() asm volatile("cp.async.commit_group;" ::: "memory")
#define CP_WAIT(n)  asm volatile("cp.async.wait_group %0;" :: "n"(n) : "memory")

__device__ __forceinline__ void mma_tf32_16x8x8(float& c0, float& c1, float& c2, float& c3,
                                                uint32_t a0, uint32_t a1, uint32_t a2, uint32_t a3,
                                                uint32_t b0, uint32_t b1) {
    asm volatile(
        "mma.sync.aligned.m16n8k8.row.col.f32.tf32.tf32.f32 "
        "{%0,%1,%2,%3}, {%4,%5,%6,%7}, {%8,%9}, {%0,%1,%2,%3};"
        : "+f"(c0), "+f"(c1), "+f"(c2), "+f"(c3)
        : "r"(a0), "r"(a1), "r"(a2), "r"(a3), "r"(b0), "r"(b1));
}

// ---------------- weight transpose: out[n*K+k] = in[k*N+n] --------------------
__global__ __launch_bounds__(256)
void transpose32(const float* __restrict__ in, float* __restrict__ out, int K, int N)
{
    __shared__ float t[32][33];
    const int bx = blockIdx.x * 32;
    const int by = blockIdx.y * 32;
    const int tx = threadIdx.x, ty = threadIdx.y;
#pragma unroll
    for (int i = 0; i < 32; i += 8)
        t[ty + i][tx] = in[(size_t)(by + ty + i) * N + bx + tx];
    __syncthreads();
#pragma unroll
    for (int i = 0; i < 32; i += 8)
        out[(size_t)(bx + ty + i) * K + by + tx] = t[tx][ty + i];
}

// ---------------- tf32 mma.sync GEMM (unchanged, validated R3) ----------------
#define GPAD 36
#define GBUF (128 * GPAD)
#define G_SMEM_BYTES (4 * GBUF * 4)

__global__ __launch_bounds__(256)
void gemm_mma(const float* __restrict__ A, const float* __restrict__ BT,
              float* __restrict__ C, int M, int N, int K)
{
    extern __shared__ float sm[];
    float* sA = sm;
    float* sB = sm + 2 * GBUF;

    const int tid  = threadIdx.x;
    const int wid  = tid >> 5;
    const int lane = tid & 31;
    const int g    = lane >> 2;
    const int tg   = lane & 3;
    const int wm   = (wid & 3) * 32;
    const int wn   = (wid >> 2) * 64;
    const int m0 = blockIdx.y * 128;
    const int n0 = blockIdx.x * 128;

    const int lrow  = tid >> 1;
    const int lcol  = (tid & 1) * 16;
    const float* gA = A  + (size_t)(m0 + lrow) * K + lcol;
    const float* gB = BT + (size_t)(n0 + lrow) * K + lcol;
    const uint32_t sbase = smem_u32(sm);
    const uint32_t sArow = sbase + (uint32_t)(lrow * GPAD + lcol) * 4u;
    const uint32_t sBrow = sArow + 2u * GBUF * 4u;

    float acc[2][8][4];
#pragma unroll
    for (int mt = 0; mt < 2; mt++)
#pragma unroll
        for (int nt = 0; nt < 8; nt++)
#pragma unroll
            for (int i = 0; i < 4; i++) acc[mt][nt][i] = 0.f;

    const int nch = K >> 5;
    {
#pragma unroll
        for (int j = 0; j < 4; j++) {
            CP_ASYNC16(sArow + j * 16u, gA + j * 4);
            CP_ASYNC16(sBrow + j * 16u, gB + j * 4);
        }
        CP_COMMIT();
    }

    for (int c = 0; c < nch; ++c) {
        const int buf = c & 1;
        if (c + 1 < nch) {
            const uint32_t off = (uint32_t)(((c + 1) & 1) * GBUF) * 4u;
            const float* pa = gA + (c + 1) * 32;
            const float* pb = gB + (c + 1) * 32;
#pragma unroll
            for (int j = 0; j < 4; j++) {
                CP_ASYNC16(sArow + off + j * 16u, pa + j * 4);
                CP_ASYNC16(sBrow + off + j * 16u, pb + j * 4);
            }
            CP_COMMIT();
            CP_WAIT(1);
        } else {
            CP_WAIT(0);
        }
        __syncthreads();

        const float* tA = sA + buf * GBUF;
        const float* tB = sB + buf * GBUF;

#pragma unroll
        for (int ks = 0; ks < 4; ++ks) {
            const int kk = ks * 8 + tg;
            uint32_t af[2][4];
#pragma unroll
            for (int mt = 0; mt < 2; mt++) {
                const int r = wm + mt * 16 + g;
                af[mt][0] = f2tf32(tA[r * GPAD + kk]);
                af[mt][1] = f2tf32(tA[(r + 8) * GPAD + kk]);
                af[mt][2] = f2tf32(tA[r * GPAD + kk + 4]);
                af[mt][3] = f2tf32(tA[(r + 8) * GPAD + kk + 4]);
            }
            uint32_t bf[8][2];
#pragma unroll
            for (int nt = 0; nt < 8; nt++) {
                const int r = wn + nt * 8 + g;
                bf[nt][0] = f2tf32(tB[r * GPAD + kk]);
                bf[nt][1] = f2tf32(tB[r * GPAD + kk + 4]);
            }
#pragma unroll
            for (int mt = 0; mt < 2; mt++)
#pragma unroll
                for (int nt = 0; nt < 8; nt++)
                    mma_tf32_16x8x8(acc[mt][nt][0], acc[mt][nt][1],
                                    acc[mt][nt][2], acc[mt][nt][3],
                                    af[mt][0], af[mt][1], af[mt][2], af[mt][3],
                                    bf[nt][0], bf[nt][1]);
        }
        __syncthreads();
    }

#pragma unroll
    for (int mt = 0; mt < 2; mt++) {
        const int r0 = m0 + wm + mt * 16 + g;
#pragma unroll
        for (int nt = 0; nt < 8; nt++) {
            const int col = n0 + wn + nt * 8 + 2 * tg;
            *(float2*)(C + (size_t)r0 * N + col) =
                make_float2(acc[mt][nt][0], acc[mt][nt][1]);
            *(float2*)(C + (size_t)(r0 + 8) * N + col) =
                make_float2(acc[mt][nt][2], acc[mt][nt][3]);
        }
    }
}

// ---------------- fused per-head RMSNorm + RoPE (in place) --------------------
__global__ __launch_bounds__(256)
void norm_rope_kernel(float* __restrict__ x, const float* __restrict__ w,
                      const int* __restrict__ pos, int nheads, int rw)
{
    const int gw = (blockIdx.x * blockDim.x + threadIdx.x) >> 5;
    const int lane = threadIdx.x & 31;
    const int total = SEQ * nheads;
    if (gw >= total) return;
    const int s = gw / nheads;
    const int hh = gw - s * nheads;

    float* p = x + (size_t)s * rw + hh * HD;
    float x0 = p[lane];
    float x1 = p[lane + 32];

    float ss = x0 * x0 + x1 * x1;
#pragma unroll
    for (int o = 16; o; o >>= 1) ss += __shfl_xor_sync(0xffffffffu, ss, o);
    const float inv = rsqrtf(ss * (1.f / 64.f) + 1e-6f);
    x0 *= inv * w[lane];
    x1 *= inv * w[lane + 32];

    const float ang = (float)pos[s] * __expf(-(float)lane * (1.f / 32.f) * 9.2103403719761836f);
    float sn, c;
    sincosf(ang, &sn, &c);
    p[lane]      = x0 * c - x1 * sn;
    p[lane + 32] = x1 * c + x0 * sn;
}

// ---------------- causal flash attention with tf32 mma.sync -------------------
// grid (SEQ/128, NH), 256 threads. Warp w owns q-rows [qt*128+w*16, +16).
// Q resides in registers as tf32 A-fragments. KV tiles of 64.
// smem: Ks[64][APAD] natural, Vt[64][APAD] transposed, Ps[8][16][APAD] per-warp.
#define APAD 68
#define AT_SMEM_FLOATS (2 * 64 * APAD + 8 * 16 * APAD)
#define AT_SMEM_BYTES  (AT_SMEM_FLOATS * 4)
#define L2E 1.4426950408889634f

__global__ __launch_bounds__(256)
void attn_mma(const float* __restrict__ qb, const float* __restrict__ kb,
              const float* __restrict__ vb, float* __restrict__ ob)
{
    extern __shared__ float sm[];
    float* Ks = sm;
    float* Vt = sm + 64 * APAD;
    float* Ps = sm + 2 * 64 * APAD;

    const int tid = threadIdx.x;
    const int wid = tid >> 5;
    const int lane = tid & 31;
    const int g = lane >> 2;
    const int tg = lane & 3;
    const int qt = blockIdx.x;
    const int h = blockIdx.y;
    const int kvh = h >> 2;

    float* Pw = Ps + wid * 16 * APAD;
    uint32_t* Pwu = (uint32_t*)Pw;

    // ---- Q fragments in registers (pre-scaled, tf32) ----
    uint32_t aq[8][4];
    {
        const float* qp = qb + (size_t)(qt * 128 + wid * 16) * HID + h * HD;
#pragma unroll
        for (int ks = 0; ks < 8; ks++) {
            const int c0 = ks * 8 + tg;
            aq[ks][0] = f2tf32(qp[(size_t)g * HID + c0] * 0.125f);
            aq[ks][1] = f2tf32(qp[(size_t)(g + 8) * HID + c0] * 0.125f);
            aq[ks][2] = f2tf32(qp[(size_t)g * HID + c0 + 4] * 0.125f);
            aq[ks][3] = f2tf32(qp[(size_t)(g + 8) * HID + c0 + 4] * 0.125f);
        }
    }

    float o[8][4];
#pragma unroll
    for (int nt = 0; nt < 8; nt++)
#pragma unroll
        for (int i = 0; i < 4; i++) o[nt][i] = 0.f;
    float m0 = -1e30f, m1 = -1e30f, l0 = 0.f, l1 = 0.f;

    const int r0g = qt * 128 + wid * 16 + g;   // row for c0/c1
    const int r1g = r0g + 8;                   // row for c2/c3
    const int nkt = 2 * qt + 2;

    for (int kt = 0; kt < nkt; ++kt) {
        // ---- cooperative load: K natural, V transposed ----
        {
            const int r = tid >> 2;
            const int c4 = (tid & 3) * 16;
            const float* kp = kb + (size_t)(kt * 64 + r) * KVW + kvh * HD + c4;
            const float* vp = vb + (size_t)(kt * 64 + r) * KVW + kvh * HD + c4;
#pragma unroll
            for (int i = 0; i < 16; i += 4) {
                float4 k4 = *(const float4*)(kp + i);
                *(float4*)(Ks + r * APAD + c4 + i) = k4;
                float4 v4 = *(const float4*)(vp + i);
                Vt[(c4 + i + 0) * APAD + r] = v4.x;
                Vt[(c4 + i + 1) * APAD + r] = v4.y;
                Vt[(c4 + i + 2) * APAD + r] = v4.z;
                Vt[(c4 + i + 3) * APAD + r] = v4.w;
            }
        }
        __syncthreads();

        const bool active = !(kt == 2 * qt + 1 && wid < 4);
        if (active) {
            // ---- S = Q @ K^T ----
            float s[8][4];
#pragma unroll
            for (int nt = 0; nt < 8; nt++)
#pragma unroll
                for (int i = 0; i < 4; i++) s[nt][i] = 0.f;

#pragma unroll
            for (int ks = 0; ks < 8; ks++) {
                const int kk = ks * 8 + tg;
#pragma unroll
                for (int nt = 0; nt < 8; nt++) {
                    const uint32_t b0 = f2tf32(Ks[(nt * 8 + g) * APAD + kk]);
                    const uint32_t b1 = f2tf32(Ks[(nt * 8 + g) * APAD + kk + 4]);
                    mma_tf32_16x8x8(s[nt][0], s[nt][1], s[nt][2], s[nt][3],
                                    aq[ks][0], aq[ks][1], aq[ks][2], aq[ks][3],
                                    b0, b1);
                }
            }

            // ---- causal mask (diagonal region) ----
            if (kt >= 2 * qt) {
#pragma unroll
                for (int nt = 0; nt < 8; nt++) {
                    const int j0 = kt * 64 + nt * 8 + 2 * tg;
                    if (j0 > r0g)     s[nt][0] = -1e30f;
                    if (j0 + 1 > r0g) s[nt][1] = -1e30f;
                    if (j0 > r1g)     s[nt][2] = -1e30f;
                    if (j0 + 1 > r1g) s[nt][3] = -1e30f;
                }
            }

            // ---- online softmax (register fragments) ----
            float mx0 = -1e30f, mx1 = -1e30f;
#pragma unroll
            for (int nt = 0; nt < 8; nt++) {
                mx0 = fmaxf(mx0, fmaxf(s[nt][0], s[nt][1]));
                mx1 = fmaxf(mx1, fmaxf(s[nt][2], s[nt][3]));
            }
            mx0 = fmaxf(mx0, __shfl_xor_sync(0xffffffffu, mx0, 1));
            mx0 = fmaxf(mx0, __shfl_xor_sync(0xffffffffu, mx0, 2));
            mx1 = fmaxf(mx1, __shfl_xor_sync(0xffffffffu, mx1, 1));
            mx1 = fmaxf(mx1, __shfl_xor_sync(0xffffffffu, mx1, 2));

            const float mn0 = fmaxf(m0, mx0);
            const float mn1 = fmaxf(m1, mx1);
            const float al0 = exp2f((m0 - mn0) * L2E);
            const float al1 = exp2f((m1 - mn1) * L2E);
            float sum0 = 0.f, sum1 = 0.f;
#pragma unroll
            for (int nt = 0; nt < 8; nt++) {
                s[nt][0] = exp2f((s[nt][0] - mn0) * L2E);
                s[nt][1] = exp2f((s[nt][1] - mn0) * L2E);
                s[nt][2] = exp2f((s[nt][2] - mn1) * L2E);
                s[nt][3] = exp2f((s[nt][3] - mn1) * L2E);
                sum0 += s[nt][0] + s[nt][1];
                sum1 += s[nt][2] + s[nt][3];
            }
            sum0 += __shfl_xor_sync(0xffffffffu, sum0, 1);
            sum0 += __shfl_xor_sync(0xffffffffu, sum0, 2);
            sum1 += __shfl_xor_sync(0xffffffffu, sum1, 1);
            sum1 += __shfl_xor_sync(0xffffffffu, sum1, 2);
            m0 = mn0; m1 = mn1;
            l0 = l0 * al0 + sum0;
            l1 = l1 * al1 + sum1;
#pragma unroll
            for (int nt = 0; nt < 8; nt++) {
                o[nt][0] *= al0; o[nt][1] *= al0;
                o[nt][2] *= al1; o[nt][3] *= al1;
            }

            // ---- stage P (pre-converted tf32) into per-warp smem ----
#pragma unroll
            for (int nt = 0; nt < 8; nt++) {
                const int c = nt * 8 + 2 * tg;
                Pwu[g * APAD + c]           = f2tf32(s[nt][0]);
                Pwu[g * APAD + c + 1]       = f2tf32(s[nt][1]);
                Pwu[(g + 8) * APAD + c]     = f2tf32(s[nt][2]);
                Pwu[(g + 8) * APAD + c + 1] = f2tf32(s[nt][3]);
            }
            __syncwarp();

            // ---- O += P @ V ----
#pragma unroll
            for (int ks = 0; ks < 8; ks++) {
                const int kk = ks * 8 + tg;
                const uint32_t a0 = Pwu[g * APAD + kk];
                const uint32_t a1 = Pwu[(g + 8) * APAD + kk];
                const uint32_t a2 = Pwu[g * APAD + kk + 4];
                const uint32_t a3 = Pwu[(g + 8) * APAD + kk + 4];
#pragma unroll
                for (int nt = 0; nt < 8; nt++) {
                    const uint32_t b0 = f2tf32(Vt[(nt * 8 + g) * APAD + kk]);
                    const uint32_t b1 = f2tf32(Vt[(nt * 8 + g) * APAD + kk + 4]);
                    mma_tf32_16x8x8(o[nt][0], o[nt][1], o[nt][2], o[nt][3],
                                    a0, a1, a2, a3, b0, b1);
                }
            }
        }
        __syncthreads();
    }

    // ---- epilogue ----
    const float il0 = 1.f / l0;
    const float il1 = 1.f / l1;
#pragma unroll
    for (int nt = 0; nt < 8; nt++) {
        const int col = h * HD + nt * 8 + 2 * tg;
        *(float2*)(ob + (size_t)r0g * HID + col) =
            make_float2(o[nt][0] * il0, o[nt][1] * il0);
        *(float2*)(ob + (size_t)r1g * HID + col) =
            make_float2(o[nt][2] * il1, o[nt][3] * il1);
    }
}

// ---------------- launch ------------------------------------------------------
extern "C" void kernel_launch(void* const* d_in, const int* in_sizes, int n_in,
                              void* d_out, int out_size)
{
    const float* hs  = (const float*)d_in[0];
    const int*   pos = (const int*)  d_in[1];
    const float* wq  = (const float*)d_in[2];
    const float* wk  = (const float*)d_in[3];
    const float* wv  = (const float*)d_in[4];
    const float* wo  = (const float*)d_in[5];
    const float* qw  = (const float*)d_in[6];
    const float* kw  = (const float*)d_in[7];
    float* out = (float*)d_out;

    float *pq, *pk, *pv, *pa, *pwqT, *pwkT, *pwvT, *pwoT;
    cudaGetSymbolAddress((void**)&pq, g_q);
    cudaGetSymbolAddress((void**)&pk, g_k);
    cudaGetSymbolAddress((void**)&pv, g_v);
    cudaGetSymbolAddress((void**)&pa, g_att);
    cudaGetSymbolAddress((void**)&pwqT, g_wqT);
    cudaGetSymbolAddress((void**)&pwkT, g_wkT);
    cudaGetSymbolAddress((void**)&pwvT, g_wvT);
    cudaGetSymbolAddress((void**)&pwoT, g_woT);

    cudaFuncSetAttribute(gemm_mma, cudaFuncAttributeMaxDynamicSharedMemorySize,
                         G_SMEM_BYTES);
    cudaFuncSetAttribute(attn_mma, cudaFuncAttributeMaxDynamicSharedMemorySize,
                         AT_SMEM_BYTES);

    dim3 tb(32, 8);
    transpose32<<<dim3(HID / 32, HID / 32), tb>>>(wq, pwqT, HID, HID);
    transpose32<<<dim3(KVW / 32, HID / 32), tb>>>(wk, pwkT, HID, KVW);
    transpose32<<<dim3(KVW / 32, HID / 32), tb>>>(wv, pwvT, HID, KVW);
    transpose32<<<dim3(HID / 32, HID / 32), tb>>>(wo, pwoT, HID, HID);

    gemm_mma<<<dim3(HID / 128, SEQ / 128), 256, G_SMEM_BYTES>>>(hs, pwqT, pq, SEQ, HID, HID);
    gemm_mma<<<dim3(KVW / 128, SEQ / 128), 256, G_SMEM_BYTES>>>(hs, pwkT, pk, SEQ, KVW, HID);
    gemm_mma<<<dim3(KVW / 128, SEQ / 128), 256, G_SMEM_BYTES>>>(hs, pwvT, pv, SEQ, KVW, HID);

    norm_rope_kernel<<<(SEQ * NH * 32) / 256, 256>>>(pq, qw, pos, NH, HID);
    norm_rope_kernel<<<(SEQ * NKV * 32) / 256, 256>>>(pk, kw, pos, NKV, KVW);

    attn_mma<<<dim3(SEQ / 128, NH), 256, AT_SMEM_BYTES>>>(pq, pk, pv, pa);

    gemm_mma<<<dim3(HID / 128, SEQ / 128), 256, G_SMEM_BYTES>>>(pa, pwoT, out, SEQ, HID, HID);
}

// round 7
// speedup vs baseline: 2.6812x; 1.0623x over previous
#include <cuda_runtime.h>
#include <math.h>
#include <stdint.h>

#define SEQ 2048
#define HID 2048
#define NH 32
#define NKV 8
#define HD 64
#define KVW (NKV*HD)   /* 512 */

// ---------------- scratch (static device arrays; no allocation) ----------------
__device__ float g_q[SEQ * HID];
__device__ float g_k[SEQ * KVW];
__device__ float g_v[SEQ * KVW];
__device__ float g_att[SEQ * HID];
__device__ float g_hs32[SEQ * HID];
__device__ float g_wqT[HID * HID];
__device__ float g_wkT[KVW * HID];
__device__ float g_wvT[KVW * HID];
__device__ float g_woT[HID * HID];

// ================= helpers =================
__device__ __forceinline__ uint32_t smem_u32(const void* p) {
    uint32_t a;
    asm("{ .reg .u64 t; cvta.to.shared.u64 t, %1; cvt.u32.u64 %0, t; }" : "=r"(a) : "l"(p));
    return a;
}
__device__ __forceinline__ uint32_t f2tf32(float f) {
    uint32_t r;
    asm("cvt.rna.tf32.f32 %0, %1;" : "=r"(r) : "f"(f));
    return r;
}
__device__ __forceinline__ float f2tf32f(float f) {
    return __uint_as_float(f2tf32(f));
}
#define CP_ASYNC16(dst, src) \
    asm volatile("cp.async.cg.shared.global [%0], [%1], 16;" :: "r"(dst), "l"(src))
#define CP_COMMIT() asm volatile("cp.async.commit_group;" ::: "memory")
#define CP_WAIT(n)  asm volatile("cp.async.wait_group %0;" :: "n"(n) : "memory")

__device__ __forceinline__ void mma_tf32_16x8x8(float& c0, float& c1, float& c2, float& c3,
                                                uint32_t a0, uint32_t a1, uint32_t a2, uint32_t a3,
                                                uint32_t b0, uint32_t b1) {
    asm volatile(
        "mma.sync.aligned.m16n8k8.row.col.f32.tf32.tf32.f32 "
        "{%0,%1,%2,%3}, {%4,%5,%6,%7}, {%8,%9}, {%0,%1,%2,%3};"
        : "+f"(c0), "+f"(c1), "+f"(c2), "+f"(c3)
        : "r"(a0), "r"(a1), "r"(a2), "r"(a3), "r"(b0), "r"(b1));
}

// ---------------- elementwise tf32-round copy ---------------------------------
__global__ __launch_bounds__(256)
void round_copy(const float* __restrict__ in, float* __restrict__ out)
{
    const int i = (blockIdx.x * 256 + threadIdx.x) * 4;
    float4 v = *(const float4*)(in + i);
    v.x = f2tf32f(v.x); v.y = f2tf32f(v.y);
    v.z = f2tf32f(v.z); v.w = f2tf32f(v.w);
    *(float4*)(out + i) = v;
}

// ---------------- weight transpose + tf32 round: out[n*K+k] = tf32(in[k*N+n]) -
__global__ __launch_bounds__(256)
void transpose32(const float* __restrict__ in, float* __restrict__ out, int K, int N)
{
    __shared__ float t[32][33];
    const int bx = blockIdx.x * 32;
    const int by = blockIdx.y * 32;
    const int tx = threadIdx.x, ty = threadIdx.y;
#pragma unroll
    for (int i = 0; i < 32; i += 8)
        t[ty + i][tx] = in[(size_t)(by + ty + i) * N + bx + tx];
    __syncthreads();
#pragma unroll
    for (int i = 0; i < 32; i += 8)
        out[(size_t)(bx + ty + i) * K + by + tx] = f2tf32f(t[tx][ty + i]);
}

// ---------------- tf32 mma.sync GEMM (inputs pre-rounded to tf32) -------------
#define GPAD 36
#define GBUF (128 * GPAD)
#define G_SMEM_BYTES (4 * GBUF * 4)

__global__ __launch_bounds__(256)
void gemm_mma(const float* __restrict__ A, const float* __restrict__ BT,
              float* __restrict__ C, int M, int N, int K)
{
    extern __shared__ float sm[];
    float* sA = sm;
    float* sB = sm + 2 * GBUF;

    const int tid  = threadIdx.x;
    const int wid  = tid >> 5;
    const int lane = tid & 31;
    const int g    = lane >> 2;
    const int tg   = lane & 3;
    const int wm   = (wid & 3) * 32;
    const int wn   = (wid >> 2) * 64;
    const int m0 = blockIdx.y * 128;
    const int n0 = blockIdx.x * 128;

    const int lrow  = tid >> 1;
    const int lcol  = (tid & 1) * 16;
    const float* gA = A  + (size_t)(m0 + lrow) * K + lcol;
    const float* gB = BT + (size_t)(n0 + lrow) * K + lcol;
    const uint32_t sbase = smem_u32(sm);
    const uint32_t sArow = sbase + (uint32_t)(lrow * GPAD + lcol) * 4u;
    const uint32_t sBrow = sArow + 2u * GBUF * 4u;

    float acc[2][8][4];
#pragma unroll
    for (int mt = 0; mt < 2; mt++)
#pragma unroll
        for (int nt = 0; nt < 8; nt++)
#pragma unroll
            for (int i = 0; i < 4; i++) acc[mt][nt][i] = 0.f;

    const int nch = K >> 5;
    {
#pragma unroll
        for (int j = 0; j < 4; j++) {
            CP_ASYNC16(sArow + j * 16u, gA + j * 4);
            CP_ASYNC16(sBrow + j * 16u, gB + j * 4);
        }
        CP_COMMIT();
    }

    for (int c = 0; c < nch; ++c) {
        const int buf = c & 1;
        if (c + 1 < nch) {
            const uint32_t off = (uint32_t)(((c + 1) & 1) * GBUF) * 4u;
            const float* pa = gA + (c + 1) * 32;
            const float* pb = gB + (c + 1) * 32;
#pragma unroll
            for (int j = 0; j < 4; j++) {
                CP_ASYNC16(sArow + off + j * 16u, pa + j * 4);
                CP_ASYNC16(sBrow + off + j * 16u, pb + j * 4);
            }
            CP_COMMIT();
            CP_WAIT(1);
        } else {
            CP_WAIT(0);
        }
        __syncthreads();

        const float* tA = sA + buf * GBUF;
        const float* tB = sB + buf * GBUF;

#pragma unroll
        for (int ks = 0; ks < 4; ++ks) {
            const int kk = ks * 8 + tg;
            uint32_t af[2][4];
#pragma unroll
            for (int mt = 0; mt < 2; mt++) {
                const int r = wm + mt * 16 + g;
                af[mt][0] = __float_as_uint(tA[r * GPAD + kk]);
                af[mt][1] = __float_as_uint(tA[(r + 8) * GPAD + kk]);
                af[mt][2] = __float_as_uint(tA[r * GPAD + kk + 4]);
                af[mt][3] = __float_as_uint(tA[(r + 8) * GPAD + kk + 4]);
            }
            uint32_t bf[8][2];
#pragma unroll
            for (int nt = 0; nt < 8; nt++) {
                const int r = wn + nt * 8 + g;
                bf[nt][0] = __float_as_uint(tB[r * GPAD + kk]);
                bf[nt][1] = __float_as_uint(tB[r * GPAD + kk + 4]);
            }
#pragma unroll
            for (int mt = 0; mt < 2; mt++)
#pragma unroll
                for (int nt = 0; nt < 8; nt++)
                    mma_tf32_16x8x8(acc[mt][nt][0], acc[mt][nt][1],
                                    acc[mt][nt][2], acc[mt][nt][3],
                                    af[mt][0], af[mt][1], af[mt][2], af[mt][3],
                                    bf[nt][0], bf[nt][1]);
        }
        __syncthreads();
    }

#pragma unroll
    for (int mt = 0; mt < 2; mt++) {
        const int r0 = m0 + wm + mt * 16 + g;
#pragma unroll
        for (int nt = 0; nt < 8; nt++) {
            const int col = n0 + wn + nt * 8 + 2 * tg;
            *(float2*)(C + (size_t)r0 * N + col) =
                make_float2(acc[mt][nt][0], acc[mt][nt][1]);
            *(float2*)(C + (size_t)(r0 + 8) * N + col) =
                make_float2(acc[mt][nt][2], acc[mt][nt][3]);
        }
    }
}

// ---------------- fused per-head RMSNorm + RoPE (in place) --------------------
__global__ __launch_bounds__(256)
void norm_rope_kernel(float* __restrict__ x, const float* __restrict__ w,
                      const int* __restrict__ pos, int nheads, int rw)
{
    const int gw = (blockIdx.x * blockDim.x + threadIdx.x) >> 5;
    const int lane = threadIdx.x & 31;
    const int total = SEQ * nheads;
    if (gw >= total) return;
    const int s = gw / nheads;
    const int hh = gw - s * nheads;

    float* p = x + (size_t)s * rw + hh * HD;
    float x0 = p[lane];
    float x1 = p[lane + 32];

    float ss = x0 * x0 + x1 * x1;
#pragma unroll
    for (int o = 16; o; o >>= 1) ss += __shfl_xor_sync(0xffffffffu, ss, o);
    const float inv = rsqrtf(ss * (1.f / 64.f) + 1e-6f);
    x0 *= inv * w[lane];
    x1 *= inv * w[lane + 32];

    const float ang = (float)pos[s] * __expf(-(float)lane * (1.f / 32.f) * 9.2103403719761836f);
    float sn, c;
    sincosf(ang, &sn, &c);
    p[lane]      = x0 * c - x1 * sn;
    p[lane + 32] = x1 * c + x0 * sn;
}

// ---------------- causal flash attention with tf32 mma.sync -------------------
// K/V stored pre-rounded to tf32 in smem; inner loops are LDS+HMMA only.
#define APAD 68
#define AT_SMEM_FLOATS (2 * 64 * APAD + 8 * 16 * APAD)
#define AT_SMEM_BYTES  (AT_SMEM_FLOATS * 4)
#define L2E 1.4426950408889634f

__global__ __launch_bounds__(256)
void attn_mma(const float* __restrict__ qb, const float* __restrict__ kb,
              const float* __restrict__ vb, float* __restrict__ ob)
{
    extern __shared__ float sm[];
    float* Ks = sm;
    float* Vt = sm + 64 * APAD;
    float* Ps = sm + 2 * 64 * APAD;

    const int tid = threadIdx.x;
    const int wid = tid >> 5;
    const int lane = tid & 31;
    const int g = lane >> 2;
    const int tg = lane & 3;
    const int qt = blockIdx.x;
    const int h = blockIdx.y;
    const int kvh = h >> 2;

    float* Pw = Ps + wid * 16 * APAD;
    uint32_t* Pwu = (uint32_t*)Pw;

    // ---- Q fragments in registers (pre-scaled, tf32) ----
    uint32_t aq[8][4];
    {
        const float* qp = qb + (size_t)(qt * 128 + wid * 16) * HID + h * HD;
#pragma unroll
        for (int ks = 0; ks < 8; ks++) {
            const int c0 = ks * 8 + tg;
            aq[ks][0] = f2tf32(qp[(size_t)g * HID + c0] * 0.125f);
            aq[ks][1] = f2tf32(qp[(size_t)(g + 8) * HID + c0] * 0.125f);
            aq[ks][2] = f2tf32(qp[(size_t)g * HID + c0 + 4] * 0.125f);
            aq[ks][3] = f2tf32(qp[(size_t)(g + 8) * HID + c0 + 4] * 0.125f);
        }
    }

    float o[8][4];
#pragma unroll
    for (int nt = 0; nt < 8; nt++)
#pragma unroll
        for (int i = 0; i < 4; i++) o[nt][i] = 0.f;
    float m0 = -1e30f, m1 = -1e30f, l0 = 0.f, l1 = 0.f;

    const int r0g = qt * 128 + wid * 16 + g;
    const int r1g = r0g + 8;
    const int nkt = 2 * qt + 2;

    for (int kt = 0; kt < nkt; ++kt) {
        // ---- cooperative load: K natural, V transposed; tf32-round at store ----
        {
            const int r = tid >> 2;
            const int c4 = (tid & 3) * 16;
            const float* kp = kb + (size_t)(kt * 64 + r) * KVW + kvh * HD + c4;
            const float* vp = vb + (size_t)(kt * 64 + r) * KVW + kvh * HD + c4;
#pragma unroll
            for (int i = 0; i < 16; i += 4) {
                float4 k4 = *(const float4*)(kp + i);
                k4.x = f2tf32f(k4.x); k4.y = f2tf32f(k4.y);
                k4.z = f2tf32f(k4.z); k4.w = f2tf32f(k4.w);
                *(float4*)(Ks + r * APAD + c4 + i) = k4;
                float4 v4 = *(const float4*)(vp + i);
                Vt[(c4 + i + 0) * APAD + r] = f2tf32f(v4.x);
                Vt[(c4 + i + 1) * APAD + r] = f2tf32f(v4.y);
                Vt[(c4 + i + 2) * APAD + r] = f2tf32f(v4.z);
                Vt[(c4 + i + 3) * APAD + r] = f2tf32f(v4.w);
            }
        }
        __syncthreads();

        const bool active = !(kt == 2 * qt + 1 && wid < 4);
        if (active) {
            // ---- S = Q @ K^T ----
            float s[8][4];
#pragma unroll
            for (int nt = 0; nt < 8; nt++)
#pragma unroll
                for (int i = 0; i < 4; i++) s[nt][i] = 0.f;

#pragma unroll
            for (int ks = 0; ks < 8; ks++) {
                const int kk = ks * 8 + tg;
#pragma unroll
                for (int nt = 0; nt < 8; nt++) {
                    const uint32_t b0 = __float_as_uint(Ks[(nt * 8 + g) * APAD + kk]);
                    const uint32_t b1 = __float_as_uint(Ks[(nt * 8 + g) * APAD + kk + 4]);
                    mma_tf32_16x8x8(s[nt][0], s[nt][1], s[nt][2], s[nt][3],
                                    aq[ks][0], aq[ks][1], aq[ks][2], aq[ks][3],
                                    b0, b1);
                }
            }

            // ---- causal mask (diagonal region) ----
            if (kt >= 2 * qt) {
#pragma unroll
                for (int nt = 0; nt < 8; nt++) {
                    const int j0 = kt * 64 + nt * 8 + 2 * tg;
                    if (j0 > r0g)     s[nt][0] = -1e30f;
                    if (j0 + 1 > r0g) s[nt][1] = -1e30f;
                    if (j0 > r1g)     s[nt][2] = -1e30f;
                    if (j0 + 1 > r1g) s[nt][3] = -1e30f;
                }
            }

            // ---- online softmax (register fragments) ----
            float mx0 = -1e30f, mx1 = -1e30f;
#pragma unroll
            for (int nt = 0; nt < 8; nt++) {
                mx0 = fmaxf(mx0, fmaxf(s[nt][0], s[nt][1]));
                mx1 = fmaxf(mx1, fmaxf(s[nt][2], s[nt][3]));
            }
            mx0 = fmaxf(mx0, __shfl_xor_sync(0xffffffffu, mx0, 1));
            mx0 = fmaxf(mx0, __shfl_xor_sync(0xffffffffu, mx0, 2));
            mx1 = fmaxf(mx1, __shfl_xor_sync(0xffffffffu, mx1, 1));
            mx1 = fmaxf(mx1, __shfl_xor_sync(0xffffffffu, mx1, 2));

            const float mn0 = fmaxf(m0, mx0);
            const float mn1 = fmaxf(m1, mx1);
            const float al0 = exp2f((m0 - mn0) * L2E);
            const float al1 = exp2f((m1 - mn1) * L2E);
            float sum0 = 0.f, sum1 = 0.f;
#pragma unroll
            for (int nt = 0; nt < 8; nt++) {
                s[nt][0] = exp2f((s[nt][0] - mn0) * L2E);
                s[nt][1] = exp2f((s[nt][1] - mn0) * L2E);
                s[nt][2] = exp2f((s[nt][2] - mn1) * L2E);
                s[nt][3] = exp2f((s[nt][3] - mn1) * L2E);
                sum0 += s[nt][0] + s[nt][1];
                sum1 += s[nt][2] + s[nt][3];
            }
            sum0 += __shfl_xor_sync(0xffffffffu, sum0, 1);
            sum0 += __shfl_xor_sync(0xffffffffu, sum0, 2);
            sum1 += __shfl_xor_sync(0xffffffffu, sum1, 1);
            sum1 += __shfl_xor_sync(0xffffffffu, sum1, 2);
            m0 = mn0; m1 = mn1;
            l0 = l0 * al0 + sum0;
            l1 = l1 * al1 + sum1;
#pragma unroll
            for (int nt = 0; nt < 8; nt++) {
                o[nt][0] *= al0; o[nt][1] *= al0;
                o[nt][2] *= al1; o[nt][3] *= al1;
            }

            // ---- stage P (pre-converted tf32) into per-warp smem ----
#pragma unroll
            for (int nt = 0; nt < 8; nt++) {
                const int c = nt * 8 + 2 * tg;
                Pwu[g * APAD + c]           = f2tf32(s[nt][0]);
                Pwu[g * APAD + c + 1]       = f2tf32(s[nt][1]);
                Pwu[(g + 8) * APAD + c]     = f2tf32(s[nt][2]);
                Pwu[(g + 8) * APAD + c + 1] = f2tf32(s[nt][3]);
            }
            __syncwarp();

            // ---- O += P @ V ----
#pragma unroll
            for (int ks = 0; ks < 8; ks++) {
                const int kk = ks * 8 + tg;
                const uint32_t a0 = Pwu[g * APAD + kk];
                const uint32_t a1 = Pwu[(g + 8) * APAD + kk];
                const uint32_t a2 = Pwu[g * APAD + kk + 4];
                const uint32_t a3 = Pwu[(g + 8) * APAD + kk + 4];
#pragma unroll
                for (int nt = 0; nt < 8; nt++) {
                    const uint32_t b0 = __float_as_uint(Vt[(nt * 8 + g) * APAD + kk]);
                    const uint32_t b1 = __float_as_uint(Vt[(nt * 8 + g) * APAD + kk + 4]);
                    mma_tf32_16x8x8(o[nt][0], o[nt][1], o[nt][2], o[nt][3],
                                    a0, a1, a2, a3, b0, b1);
                }
            }
        }
        __syncthreads();
    }

    // ---- epilogue: tf32-round (feeds O-proj GEMM A-operand) ----
    const float il0 = 1.f / l0;
    const float il1 = 1.f / l1;
#pragma unroll
    for (int nt = 0; nt < 8; nt++) {
        const int col = h * HD + nt * 8 + 2 * tg;
        *(float2*)(ob + (size_t)r0g * HID + col) =
            make_float2(f2tf32f(o[nt][0] * il0), f2tf32f(o[nt][1] * il0));
        *(float2*)(ob + (size_t)r1g * HID + col) =
            make_float2(f2tf32f(o[nt][2] * il1), f2tf32f(o[nt][3] * il1));
    }
}

// ---------------- launch ------------------------------------------------------
extern "C" void kernel_launch(void* const* d_in, const int* in_sizes, int n_in,
                              void* d_out, int out_size)
{
    const float* hs  = (const float*)d_in[0];
    const int*   pos = (const int*)  d_in[1];
    const float* wq  = (const float*)d_in[2];
    const float* wk  = (const float*)d_in[3];
    const float* wv  = (const float*)d_in[4];
    const float* wo  = (const float*)d_in[5];
    const float* qw  = (const float*)d_in[6];
    const float* kw  = (const float*)d_in[7];
    float* out = (float*)d_out;

    float *pq, *pk, *pv, *pa, *phs, *pwqT, *pwkT, *pwvT, *pwoT;
    cudaGetSymbolAddress((void**)&pq, g_q);
    cudaGetSymbolAddress((void**)&pk, g_k);
    cudaGetSymbolAddress((void**)&pv, g_v);
    cudaGetSymbolAddress((void**)&pa, g_att);
    cudaGetSymbolAddress((void**)&phs, g_hs32);
    cudaGetSymbolAddress((void**)&pwqT, g_wqT);
    cudaGetSymbolAddress((void**)&pwkT, g_wkT);
    cudaGetSymbolAddress((void**)&pwvT, g_wvT);
    cudaGetSymbolAddress((void**)&pwoT, g_woT);

    cudaFuncSetAttribute(gemm_mma, cudaFuncAttributeMaxDynamicSharedMemorySize,
                         G_SMEM_BYTES);
    cudaFuncSetAttribute(attn_mma, cudaFuncAttributeMaxDynamicSharedMemorySize,
                         AT_SMEM_BYTES);

    dim3 tb(32, 8);
    round_copy<<<(SEQ * HID) / 1024, 256>>>(hs, phs);
    transpose32<<<dim3(HID / 32, HID / 32), tb>>>(wq, pwqT, HID, HID);
    transpose32<<<dim3(KVW / 32, HID / 32), tb>>>(wk, pwkT, HID, KVW);
    transpose32<<<dim3(KVW / 32, HID / 32), tb>>>(wv, pwvT, HID, KVW);
    transpose32<<<dim3(HID / 32, HID / 32), tb>>>(wo, pwoT, HID, HID);

    gemm_mma<<<dim3(HID / 128, SEQ / 128), 256, G_SMEM_BYTES>>>(phs, pwqT, pq, SEQ, HID, HID);
    gemm_mma<<<dim3(KVW / 128, SEQ / 128), 256, G_SMEM_BYTES>>>(phs, pwkT, pk, SEQ, KVW, HID);
    gemm_mma<<<dim3(KVW / 128, SEQ / 128), 256, G_SMEM_BYTES>>>(phs, pwvT, pv, SEQ, KVW, HID);

    norm_rope_kernel<<<(SEQ * NH * 32) / 256, 256>>>(pq, qw, pos, NH, HID);
    norm_rope_kernel<<<(SEQ * NKV * 32) / 256, 256>>>(pk, kw, pos, NKV, KVW);

    attn_mma<<<dim3(SEQ / 128, NH), 256, AT_SMEM_BYTES>>>(pq, pk, pv, pa);

    gemm_mma<<<dim3(HID / 128, SEQ / 128), 256, G_SMEM_BYTES>>>(pa, pwoT, out, SEQ, HID, HID);
}

// round 8
// speedup vs baseline: 3.0682x; 1.1444x over previous
#include <cuda_runtime.h>
#include <math.h>
#include <stdint.h>

#define SEQ 2048
#define HID 2048
#define NH 32
#define NKV 8
#define HD 64
#define KVW (NKV*HD)      /* 512 */
#define QKVW (HID + 2*KVW) /* 3072: fused q|k|v row width */

// ---------------- scratch (static device arrays; no allocation) ----------------
__device__ float g_qkv[SEQ * QKVW];     // fused projections: q|k|v per row
__device__ float g_att[SEQ * HID];
__device__ float g_hs32[SEQ * HID];
__device__ float g_wqkvT[QKVW * HID];   // rows 0..2047 = wq^T, 2048..2559 = wk^T, 2560..3071 = wv^T
__device__ float g_woT[HID * HID];

// ================= helpers =================
__device__ __forceinline__ uint32_t smem_u32(const void* p) {
    uint32_t a;
    asm("{ .reg .u64 t; cvta.to.shared.u64 t, %1; cvt.u32.u64 %0, t; }" : "=r"(a) : "l"(p));
    return a;
}
__device__ __forceinline__ uint32_t f2tf32(float f) {
    uint32_t r;
    asm("cvt.rna.tf32.f32 %0, %1;" : "=r"(r) : "f"(f));
    return r;
}
__device__ __forceinline__ float f2tf32f(float f) {
    return __uint_as_float(f2tf32(f));
}
#define CP_ASYNC16(dst, src) \
    asm volatile("cp.async.cg.shared.global [%0], [%1], 16;" :: "r"(dst), "l"(src))
#define CP_COMMIT() asm volatile("cp.async.commit_group;" ::: "memory")
#define CP_WAIT(n)  asm volatile("cp.async.wait_group %0;" :: "n"(n) : "memory")

__device__ __forceinline__ void mma_tf32_16x8x8(float& c0, float& c1, float& c2, float& c3,
                                                uint32_t a0, uint32_t a1, uint32_t a2, uint32_t a3,
                                                uint32_t b0, uint32_t b1) {
    asm volatile(
        "mma.sync.aligned.m16n8k8.row.col.f32.tf32.tf32.f32 "
        "{%0,%1,%2,%3}, {%4,%5,%6,%7}, {%8,%9}, {%0,%1,%2,%3};"
        : "+f"(c0), "+f"(c1), "+f"(c2), "+f"(c3)
        : "r"(a0), "r"(a1), "r"(a2), "r"(a3), "r"(b0), "r"(b1));
}

// ---------------- elementwise tf32-round copy ---------------------------------
__global__ __launch_bounds__(256)
void round_copy(const float* __restrict__ in, float* __restrict__ out)
{
    const int i = (blockIdx.x * 256 + threadIdx.x) * 4;
    float4 v = *(const float4*)(in + i);
    v.x = f2tf32f(v.x); v.y = f2tf32f(v.y);
    v.z = f2tf32f(v.z); v.w = f2tf32f(v.w);
    *(float4*)(out + i) = v;
}

// ---------------- weight transpose + tf32 round: out[n*K+k] = tf32(in[k*N+n]) -
__global__ __launch_bounds__(256)
void transpose32(const float* __restrict__ in, float* __restrict__ out, int K, int N)
{
    __shared__ float t[32][33];
    const int bx = blockIdx.x * 32;
    const int by = blockIdx.y * 32;
    const int tx = threadIdx.x, ty = threadIdx.y;
#pragma unroll
    for (int i = 0; i < 32; i += 8)
        t[ty + i][tx] = in[(size_t)(by + ty + i) * N + bx + tx];
    __syncthreads();
#pragma unroll
    for (int i = 0; i < 32; i += 8)
        out[(size_t)(bx + ty + i) * K + by + tx] = f2tf32f(t[tx][ty + i]);
}

// ---------------- tf32 mma.sync GEMM (inputs pre-rounded to tf32) -------------
#define GPAD 36
#define GBUF (128 * GPAD)
#define G_SMEM_BYTES (4 * GBUF * 4)

__global__ __launch_bounds__(256)
void gemm_mma(const float* __restrict__ A, const float* __restrict__ BT,
              float* __restrict__ C, int M, int N, int K)
{
    extern __shared__ float sm[];
    float* sA = sm;
    float* sB = sm + 2 * GBUF;

    const int tid  = threadIdx.x;
    const int wid  = tid >> 5;
    const int lane = tid & 31;
    const int g    = lane >> 2;
    const int tg   = lane & 3;
    const int wm   = (wid & 3) * 32;
    const int wn   = (wid >> 2) * 64;
    const int m0 = blockIdx.y * 128;
    const int n0 = blockIdx.x * 128;

    const int lrow  = tid >> 1;
    const int lcol  = (tid & 1) * 16;
    const float* gA = A  + (size_t)(m0 + lrow) * K + lcol;
    const float* gB = BT + (size_t)(n0 + lrow) * K + lcol;
    const uint32_t sbase = smem_u32(sm);
    const uint32_t sArow = sbase + (uint32_t)(lrow * GPAD + lcol) * 4u;
    const uint32_t sBrow = sArow + 2u * GBUF * 4u;

    float acc[2][8][4];
#pragma unroll
    for (int mt = 0; mt < 2; mt++)
#pragma unroll
        for (int nt = 0; nt < 8; nt++)
#pragma unroll
            for (int i = 0; i < 4; i++) acc[mt][nt][i] = 0.f;

    const int nch = K >> 5;
    {
#pragma unroll
        for (int j = 0; j < 4; j++) {
            CP_ASYNC16(sArow + j * 16u, gA + j * 4);
            CP_ASYNC16(sBrow + j * 16u, gB + j * 4);
        }
        CP_COMMIT();
    }

    for (int c = 0; c < nch; ++c) {
        const int buf = c & 1;
        if (c + 1 < nch) {
            const uint32_t off = (uint32_t)(((c + 1) & 1) * GBUF) * 4u;
            const float* pa = gA + (c + 1) * 32;
            const float* pb = gB + (c + 1) * 32;
#pragma unroll
            for (int j = 0; j < 4; j++) {
                CP_ASYNC16(sArow + off + j * 16u, pa + j * 4);
                CP_ASYNC16(sBrow + off + j * 16u, pb + j * 4);
            }
            CP_COMMIT();
            CP_WAIT(1);
        } else {
            CP_WAIT(0);
        }
        __syncthreads();

        const float* tA = sA + buf * GBUF;
        const float* tB = sB + buf * GBUF;

#pragma unroll
        for (int ks = 0; ks < 4; ++ks) {
            const int kk = ks * 8 + tg;
            uint32_t af[2][4];
#pragma unroll
            for (int mt = 0; mt < 2; mt++) {
                const int r = wm + mt * 16 + g;
                af[mt][0] = __float_as_uint(tA[r * GPAD + kk]);
                af[mt][1] = __float_as_uint(tA[(r + 8) * GPAD + kk]);
                af[mt][2] = __float_as_uint(tA[r * GPAD + kk + 4]);
                af[mt][3] = __float_as_uint(tA[(r + 8) * GPAD + kk + 4]);
            }
            uint32_t bf[8][2];
#pragma unroll
            for (int nt = 0; nt < 8; nt++) {
                const int r = wn + nt * 8 + g;
                bf[nt][0] = __float_as_uint(tB[r * GPAD + kk]);
                bf[nt][1] = __float_as_uint(tB[r * GPAD + kk + 4]);
            }
#pragma unroll
            for (int mt = 0; mt < 2; mt++)
#pragma unroll
                for (int nt = 0; nt < 8; nt++)
                    mma_tf32_16x8x8(acc[mt][nt][0], acc[mt][nt][1],
                                    acc[mt][nt][2], acc[mt][nt][3],
                                    af[mt][0], af[mt][1], af[mt][2], af[mt][3],
                                    bf[nt][0], bf[nt][1]);
        }
        __syncthreads();
    }

#pragma unroll
    for (int mt = 0; mt < 2; mt++) {
        const int r0 = m0 + wm + mt * 16 + g;
#pragma unroll
        for (int nt = 0; nt < 8; nt++) {
            const int col = n0 + wn + nt * 8 + 2 * tg;
            *(float2*)(C + (size_t)r0 * N + col) =
                make_float2(acc[mt][nt][0], acc[mt][nt][1]);
            *(float2*)(C + (size_t)(r0 + 8) * N + col) =
                make_float2(acc[mt][nt][2], acc[mt][nt][3]);
        }
    }
}

// ---------------- fused per-head RMSNorm + RoPE (in place) --------------------
__global__ __launch_bounds__(256)
void norm_rope_kernel(float* __restrict__ x, const float* __restrict__ w,
                      const int* __restrict__ pos, int nheads, int rw)
{
    const int gw = (blockIdx.x * blockDim.x + threadIdx.x) >> 5;
    const int lane = threadIdx.x & 31;
    const int total = SEQ * nheads;
    if (gw >= total) return;
    const int s = gw / nheads;
    const int hh = gw - s * nheads;

    float* p = x + (size_t)s * rw + hh * HD;
    float x0 = p[lane];
    float x1 = p[lane + 32];

    float ss = x0 * x0 + x1 * x1;
#pragma unroll
    for (int o = 16; o; o >>= 1) ss += __shfl_xor_sync(0xffffffffu, ss, o);
    const float inv = rsqrtf(ss * (1.f / 64.f) + 1e-6f);
    x0 *= inv * w[lane];
    x1 *= inv * w[lane + 32];

    const float ang = (float)pos[s] * __expf(-(float)lane * (1.f / 32.f) * 9.2103403719761836f);
    float sn, c;
    sincosf(ang, &sn, &c);
    p[lane]      = x0 * c - x1 * sn;
    p[lane + 32] = x1 * c + x0 * sn;
}

// ---------------- causal flash attention with tf32 mma.sync -------------------
// K/V pre-rounded at STS; inner loops pure LDS+HMMA. LPT block ordering.
#define APAD 68
#define AT_SMEM_FLOATS (2 * 64 * APAD + 8 * 16 * APAD)
#define AT_SMEM_BYTES  (AT_SMEM_FLOATS * 4)
#define L2E 1.4426950408889634f

__global__ __launch_bounds__(256)
void attn_mma(const float* __restrict__ qb, const float* __restrict__ kb,
              const float* __restrict__ vb, float* __restrict__ ob,
              int ldq, int ldkv)
{
    extern __shared__ float sm[];
    float* Ks = sm;
    float* Vt = sm + 64 * APAD;
    float* Ps = sm + 2 * 64 * APAD;

    const int tid = threadIdx.x;
    const int wid = tid >> 5;
    const int lane = tid & 31;
    const int g = lane >> 2;
    const int tg = lane & 3;
    const int qt = (int)gridDim.x - 1 - (int)blockIdx.x;  // LPT: heavy tiles first
    const int h = blockIdx.y;
    const int kvh = h >> 2;

    float* Pw = Ps + wid * 16 * APAD;
    uint32_t* Pwu = (uint32_t*)Pw;

    // ---- Q fragments in registers (pre-scaled, tf32) ----
    uint32_t aq[8][4];
    {
        const float* qp = qb + (size_t)(qt * 128 + wid * 16) * ldq + h * HD;
#pragma unroll
        for (int ks = 0; ks < 8; ks++) {
            const int c0 = ks * 8 + tg;
            aq[ks][0] = f2tf32(qp[(size_t)g * ldq + c0] * 0.125f);
            aq[ks][1] = f2tf32(qp[(size_t)(g + 8) * ldq + c0] * 0.125f);
            aq[ks][2] = f2tf32(qp[(size_t)g * ldq + c0 + 4] * 0.125f);
            aq[ks][3] = f2tf32(qp[(size_t)(g + 8) * ldq + c0 + 4] * 0.125f);
        }
    }

    float o[8][4];
#pragma unroll
    for (int nt = 0; nt < 8; nt++)
#pragma unroll
        for (int i = 0; i < 4; i++) o[nt][i] = 0.f;
    float m0 = -1e30f, m1 = -1e30f, l0 = 0.f, l1 = 0.f;

    const int r0g = qt * 128 + wid * 16 + g;
    const int r1g = r0g + 8;
    const int nkt = 2 * qt + 2;

    for (int kt = 0; kt < nkt; ++kt) {
        // ---- cooperative load: K natural, V transposed; tf32-round at store ----
        {
            const int r = tid >> 2;
            const int c4 = (tid & 3) * 16;
            const float* kp = kb + (size_t)(kt * 64 + r) * ldkv + kvh * HD + c4;
            const float* vp = vb + (size_t)(kt * 64 + r) * ldkv + kvh * HD + c4;
#pragma unroll
            for (int i = 0; i < 16; i += 4) {
                float4 k4 = *(const float4*)(kp + i);
                k4.x = f2tf32f(k4.x); k4.y = f2tf32f(k4.y);
                k4.z = f2tf32f(k4.z); k4.w = f2tf32f(k4.w);
                *(float4*)(Ks + r * APAD + c4 + i) = k4;
                float4 v4 = *(const float4*)(vp + i);
                Vt[(c4 + i + 0) * APAD + r] = f2tf32f(v4.x);
                Vt[(c4 + i + 1) * APAD + r] = f2tf32f(v4.y);
                Vt[(c4 + i + 2) * APAD + r] = f2tf32f(v4.z);
                Vt[(c4 + i + 3) * APAD + r] = f2tf32f(v4.w);
            }
        }
        __syncthreads();

        const bool active = !(kt == 2 * qt + 1 && wid < 4);
        if (active) {
            // ---- S = Q @ K^T ----
            float s[8][4];
#pragma unroll
            for (int nt = 0; nt < 8; nt++)
#pragma unroll
                for (int i = 0; i < 4; i++) s[nt][i] = 0.f;

#pragma unroll
            for (int ks = 0; ks < 8; ks++) {
                const int kk = ks * 8 + tg;
#pragma unroll
                for (int nt = 0; nt < 8; nt++) {
                    const uint32_t b0 = __float_as_uint(Ks[(nt * 8 + g) * APAD + kk]);
                    const uint32_t b1 = __float_as_uint(Ks[(nt * 8 + g) * APAD + kk + 4]);
                    mma_tf32_16x8x8(s[nt][0], s[nt][1], s[nt][2], s[nt][3],
                                    aq[ks][0], aq[ks][1], aq[ks][2], aq[ks][3],
                                    b0, b1);
                }
            }

            // ---- causal mask (diagonal region) ----
            if (kt >= 2 * qt) {
#pragma unroll
                for (int nt = 0; nt < 8; nt++) {
                    const int j0 = kt * 64 + nt * 8 + 2 * tg;
                    if (j0 > r0g)     s[nt][0] = -1e30f;
                    if (j0 + 1 > r0g) s[nt][1] = -1e30f;
                    if (j0 > r1g)     s[nt][2] = -1e30f;
                    if (j0 + 1 > r1g) s[nt][3] = -1e30f;
                }
            }

            // ---- online softmax (register fragments) ----
            float mx0 = -1e30f, mx1 = -1e30f;
#pragma unroll
            for (int nt = 0; nt < 8; nt++) {
                mx0 = fmaxf(mx0, fmaxf(s[nt][0], s[nt][1]));
                mx1 = fmaxf(mx1, fmaxf(s[nt][2], s[nt][3]));
            }
            mx0 = fmaxf(mx0, __shfl_xor_sync(0xffffffffu, mx0, 1));
            mx0 = fmaxf(mx0, __shfl_xor_sync(0xffffffffu, mx0, 2));
            mx1 = fmaxf(mx1, __shfl_xor_sync(0xffffffffu, mx1, 1));
            mx1 = fmaxf(mx1, __shfl_xor_sync(0xffffffffu, mx1, 2));

            const float mn0 = fmaxf(m0, mx0);
            const float mn1 = fmaxf(m1, mx1);
            const float al0 = exp2f((m0 - mn0) * L2E);
            const float al1 = exp2f((m1 - mn1) * L2E);
            float sum0 = 0.f, sum1 = 0.f;
#pragma unroll
            for (int nt = 0; nt < 8; nt++) {
                s[nt][0] = exp2f((s[nt][0] - mn0) * L2E);
                s[nt][1] = exp2f((s[nt][1] - mn0) * L2E);
                s[nt][2] = exp2f((s[nt][2] - mn1) * L2E);
                s[nt][3] = exp2f((s[nt][3] - mn1) * L2E);
                sum0 += s[nt][0] + s[nt][1];
                sum1 += s[nt][2] + s[nt][3];
            }
            sum0 += __shfl_xor_sync(0xffffffffu, sum0, 1);
            sum0 += __shfl_xor_sync(0xffffffffu, sum0, 2);
            sum1 += __shfl_xor_sync(0xffffffffu, sum1, 1);
            sum1 += __shfl_xor_sync(0xffffffffu, sum1, 2);
            m0 = mn0; m1 = mn1;
            l0 = l0 * al0 + sum0;
            l1 = l1 * al1 + sum1;
#pragma unroll
            for (int nt = 0; nt < 8; nt++) {
                o[nt][0] *= al0; o[nt][1] *= al0;
                o[nt][2] *= al1; o[nt][3] *= al1;
            }

            // ---- stage P (pre-converted tf32) into per-warp smem ----
#pragma unroll
            for (int nt = 0; nt < 8; nt++) {
                const int c = nt * 8 + 2 * tg;
                Pwu[g * APAD + c]           = f2tf32(s[nt][0]);
                Pwu[g * APAD + c + 1]       = f2tf32(s[nt][1]);
                Pwu[(g + 8) * APAD + c]     = f2tf32(s[nt][2]);
                Pwu[(g + 8) * APAD + c + 1] = f2tf32(s[nt][3]);
            }
            __syncwarp();

            // ---- O += P @ V ----
#pragma unroll
            for (int ks = 0; ks < 8; ks++) {
                const int kk = ks * 8 + tg;
                const uint32_t a0 = Pwu[g * APAD + kk];
                const uint32_t a1 = Pwu[(g + 8) * APAD + kk];
                const uint32_t a2 = Pwu[g * APAD + kk + 4];
                const uint32_t a3 = Pwu[(g + 8) * APAD + kk + 4];
#pragma unroll
                for (int nt = 0; nt < 8; nt++) {
                    const uint32_t b0 = __float_as_uint(Vt[(nt * 8 + g) * APAD + kk]);
                    const uint32_t b1 = __float_as_uint(Vt[(nt * 8 + g) * APAD + kk + 4]);
                    mma_tf32_16x8x8(o[nt][0], o[nt][1], o[nt][2], o[nt][3],
                                    a0, a1, a2, a3, b0, b1);
                }
            }
        }
        __syncthreads();
    }

    // ---- epilogue: tf32-round (feeds O-proj GEMM A-operand) ----
    const float il0 = 1.f / l0;
    const float il1 = 1.f / l1;
#pragma unroll
    for (int nt = 0; nt < 8; nt++) {
        const int col = h * HD + nt * 8 + 2 * tg;
        *(float2*)(ob + (size_t)r0g * HID + col) =
            make_float2(f2tf32f(o[nt][0] * il0), f2tf32f(o[nt][1] * il0));
        *(float2*)(ob + (size_t)r1g * HID + col) =
            make_float2(f2tf32f(o[nt][2] * il1), f2tf32f(o[nt][3] * il1));
    }
}

// ---------------- launch ------------------------------------------------------
extern "C" void kernel_launch(void* const* d_in, const int* in_sizes, int n_in,
                              void* d_out, int out_size)
{
    const float* hs  = (const float*)d_in[0];
    const int*   pos = (const int*)  d_in[1];
    const float* wq  = (const float*)d_in[2];
    const float* wk  = (const float*)d_in[3];
    const float* wv  = (const float*)d_in[4];
    const float* wo  = (const float*)d_in[5];
    const float* qw  = (const float*)d_in[6];
    const float* kw  = (const float*)d_in[7];
    float* out = (float*)d_out;

    float *pqkv, *pa, *phs, *pwqkvT, *pwoT;
    cudaGetSymbolAddress((void**)&pqkv, g_qkv);
    cudaGetSymbolAddress((void**)&pa, g_att);
    cudaGetSymbolAddress((void**)&phs, g_hs32);
    cudaGetSymbolAddress((void**)&pwqkvT, g_wqkvT);
    cudaGetSymbolAddress((void**)&pwoT, g_woT);

    cudaFuncSetAttribute(gemm_mma, cudaFuncAttributeMaxDynamicSharedMemorySize,
                         G_SMEM_BYTES);
    cudaFuncSetAttribute(attn_mma, cudaFuncAttributeMaxDynamicSharedMemorySize,
                         AT_SMEM_BYTES);

    dim3 tb(32, 8);
    round_copy<<<(SEQ * HID) / 1024, 256>>>(hs, phs);
    // combined transposed weight: rows [0,2048) q, [2048,2560) k, [2560,3072) v
    transpose32<<<dim3(HID / 32, HID / 32), tb>>>(wq, pwqkvT, HID, HID);
    transpose32<<<dim3(KVW / 32, HID / 32), tb>>>(wk, pwqkvT + (size_t)HID * HID, HID, KVW);
    transpose32<<<dim3(KVW / 32, HID / 32), tb>>>(wv, pwqkvT + (size_t)(HID + KVW) * HID, HID, KVW);
    transpose32<<<dim3(HID / 32, HID / 32), tb>>>(wo, pwoT, HID, HID);

    // fused QKV projection: C[2048, 3072]
    gemm_mma<<<dim3(QKVW / 128, SEQ / 128), 256, G_SMEM_BYTES>>>(phs, pwqkvT, pqkv, SEQ, QKVW, HID);

    float* pk = pqkv + HID;        // k columns [2048, 2560)
    float* pv = pqkv + HID + KVW;  // v columns [2560, 3072)
    norm_rope_kernel<<<(SEQ * NH * 32) / 256, 256>>>(pqkv, qw, pos, NH, QKVW);
    norm_rope_kernel<<<(SEQ * NKV * 32) / 256, 256>>>(pk, kw, pos, NKV, QKVW);

    attn_mma<<<dim3(SEQ / 128, NH), 256, AT_SMEM_BYTES>>>(pqkv, pk, pv, pa, QKVW, QKVW);

    gemm_mma<<<dim3(HID / 128, SEQ / 128), 256, G_SMEM_BYTES>>>(pa, pwoT, out, SEQ, HID, HID);
}